// round 13
// baseline (speedup 1.0000x reference)
#include <cuda_runtime.h>

// CustomSoftmaxExperts, threshold-only form (top-5 condition is vacuous:
// softmax values sum to 1, so any value >= 0.2 has at most 4 values above
// it and is automatically >= the 5th-largest).
//
// Layout: 8 lanes per row, 2 float4 per lane per row, 4 rows per thread.
//  - 8 LDG.128 per thread issued up front (MLP=8); each warp-load covers
//    exactly 4 cache lines (perfect coalescing).
//  - 4 independent reduction chains (rows a,b,c,d) interleaved: the 26-cyc
//    SHFL latency of each chain is hidden by issuing the other three.
//  - streaming stores (__stcs) keep the re-read input resident in L2.

#define THRESHOLD 0.2f

__global__ __launch_bounds__(256)
void softmax_thresh_kernel(const float4* __restrict__ in,
                           float4* __restrict__ out,
                           int nrows)
{
    const int t   = blockIdx.x * blockDim.x + threadIdx.x;
    const int grp = t >> 3;             // handles rows 4*grp .. 4*grp+3
    const int l8  = threadIdx.x & 7;
    if (4 * grp >= nrows) return;

    const unsigned FULL = 0xFFFFFFFFu;

    // Row = 16 float4s; 4 rows = 64 float4s per group.
    const size_t base = (size_t)grp * 64 + l8;
    float4 a0 = in[base];        float4 a1 = in[base + 8];    // row 0
    float4 b0 = in[base + 16];   float4 b1 = in[base + 24];   // row 1
    float4 c0 = in[base + 32];   float4 c1 = in[base + 40];   // row 2
    float4 d0 = in[base + 48];   float4 d1 = in[base + 56];   // row 3

    // ---- local max per row ----
    float ma = fmaxf(fmaxf(fmaxf(a0.x, a0.y), fmaxf(a0.z, a0.w)),
                     fmaxf(fmaxf(a1.x, a1.y), fmaxf(a1.z, a1.w)));
    float mb = fmaxf(fmaxf(fmaxf(b0.x, b0.y), fmaxf(b0.z, b0.w)),
                     fmaxf(fmaxf(b1.x, b1.y), fmaxf(b1.z, b1.w)));
    float mc = fmaxf(fmaxf(fmaxf(c0.x, c0.y), fmaxf(c0.z, c0.w)),
                     fmaxf(fmaxf(c1.x, c1.y), fmaxf(c1.z, c1.w)));
    float md = fmaxf(fmaxf(fmaxf(d0.x, d0.y), fmaxf(d0.z, d0.w)),
                     fmaxf(fmaxf(d1.x, d1.y), fmaxf(d1.z, d1.w)));

    // ---- row max: 3 shuffles, 4 chains interleaved ----
    #pragma unroll
    for (int o = 4; o; o >>= 1) {
        ma = fmaxf(ma, __shfl_xor_sync(FULL, ma, o));
        mb = fmaxf(mb, __shfl_xor_sync(FULL, mb, o));
        mc = fmaxf(mc, __shfl_xor_sync(FULL, mc, o));
        md = fmaxf(md, __shfl_xor_sync(FULL, md, o));
    }

    // ---- exp (32 independent MUFU ops), overwrite inputs to cap regs ----
    a0.x = __expf(a0.x - ma); a0.y = __expf(a0.y - ma);
    a0.z = __expf(a0.z - ma); a0.w = __expf(a0.w - ma);
    a1.x = __expf(a1.x - ma); a1.y = __expf(a1.y - ma);
    a1.z = __expf(a1.z - ma); a1.w = __expf(a1.w - ma);
    b0.x = __expf(b0.x - mb); b0.y = __expf(b0.y - mb);
    b0.z = __expf(b0.z - mb); b0.w = __expf(b0.w - mb);
    b1.x = __expf(b1.x - mb); b1.y = __expf(b1.y - mb);
    b1.z = __expf(b1.z - mb); b1.w = __expf(b1.w - mb);
    c0.x = __expf(c0.x - mc); c0.y = __expf(c0.y - mc);
    c0.z = __expf(c0.z - mc); c0.w = __expf(c0.w - mc);
    c1.x = __expf(c1.x - mc); c1.y = __expf(c1.y - mc);
    c1.z = __expf(c1.z - mc); c1.w = __expf(c1.w - mc);
    d0.x = __expf(d0.x - md); d0.y = __expf(d0.y - md);
    d0.z = __expf(d0.z - md); d0.w = __expf(d0.w - md);
    d1.x = __expf(d1.x - md); d1.y = __expf(d1.y - md);
    d1.z = __expf(d1.z - md); d1.w = __expf(d1.w - md);

    float sa = ((a0.x + a0.y) + (a0.z + a0.w)) + ((a1.x + a1.y) + (a1.z + a1.w));
    float sb = ((b0.x + b0.y) + (b0.z + b0.w)) + ((b1.x + b1.y) + (b1.z + b1.w));
    float sc = ((c0.x + c0.y) + (c0.z + c0.w)) + ((c1.x + c1.y) + (c1.z + c1.w));
    float sd = ((d0.x + d0.y) + (d0.z + d0.w)) + ((d1.x + d1.y) + (d1.z + d1.w));

    // ---- row sum: 3 shuffles, 4 chains interleaved ----
    #pragma unroll
    for (int o = 4; o; o >>= 1) {
        sa += __shfl_xor_sync(FULL, sa, o);
        sb += __shfl_xor_sync(FULL, sb, o);
        sc += __shfl_xor_sync(FULL, sc, o);
        sd += __shfl_xor_sync(FULL, sd, o);
    }
    float ia = __frcp_rn(sa);
    float ib = __frcp_rn(sb);
    float ic = __frcp_rn(sc);
    float id = __frcp_rn(sd);

    // ---- softmax + threshold, 8 streaming STG.128 ----
    float4 o4; float v;
    #define EMIT(E, INV, OFF)                            \
        v = (E).x * (INV); o4.x = (v >= THRESHOLD) ? v : 0.0f; \
        v = (E).y * (INV); o4.y = (v >= THRESHOLD) ? v : 0.0f; \
        v = (E).z * (INV); o4.z = (v >= THRESHOLD) ? v : 0.0f; \
        v = (E).w * (INV); o4.w = (v >= THRESHOLD) ? v : 0.0f; \
        __stcs(&out[base + (OFF)], o4);

    EMIT(a0, ia, 0)   EMIT(a1, ia, 8)
    EMIT(b0, ib, 16)  EMIT(b1, ib, 24)
    EMIT(c0, ic, 32)  EMIT(c1, ic, 40)
    EMIT(d0, id, 48)  EMIT(d1, id, 56)
    #undef EMIT
}

extern "C" void kernel_launch(void* const* d_in, const int* in_sizes, int n_in,
                              void* d_out, int out_size)
{
    const float4* in  = (const float4*)d_in[0];
    float4*       out = (float4*)d_out;
    int nrows = in_sizes[0] / 64;      // 262144

    const int threads = 256;           // 128 rows per block (4 per thread)
    int total = nrows * 2;             // 8 lanes/row, 4 rows/thread
    int blocks = (total + threads - 1) / threads;
    softmax_thresh_kernel<<<blocks, threads>>>(in, out, nrows);
}